// round 16
// baseline (speedup 1.0000x reference)
#include <cuda_runtime.h>
#include <cstdint>

#define BB 32
#define NN 128
#define NIN 16
#define MHID 64
#define MOUT 64
#define NHID 64
#define NOUT 16
#define KT 4
#define EDGES (NN * (NN - 1))

// Scratch (no cudaMalloc allowed)
__device__ float g_U[BB * NN * KT * MHID];    // [b][n][k][h] sender proj
__device__ float g_V[BB * NN * KT * MHID];    // [b][n][k][h] receiver proj + b1
__device__ float g_W2T[KT * MOUT * MHID];     // W2 transposed [k][m][kk], tf32
__device__ float g_AGGp[KT][BB * NN * MOUT];  // per-k partial aggregates

// ---------------- helpers ----------------
__device__ __forceinline__ uint32_t smem_u32(const void* p) {
    uint32_t a;
    asm("{ .reg .u64 t; cvta.to.shared.u64 t, %1; cvt.u32.u64 %0, t; }" : "=r"(a) : "l"(p));
    return a;
}
__device__ __forceinline__ uint32_t f2tf32(float x) {
    uint32_t r; asm("cvt.rna.tf32.f32 %0, %1;" : "=r"(r) : "f"(x)); return r;
}

#if defined(__CUDA_ARCH_FEAT_SM103_ALL)
__device__ __forceinline__ void mma_tf32_ss(uint32_t d, uint64_t a, uint64_t b,
                                            uint32_t idesc, uint32_t en) {
    asm volatile(
        "{\n\t.reg .pred p;\n\tsetp.ne.u32 p, %4, 0;\n\t"
        "tcgen05.mma.cta_group::1.kind::tf32 [%0], %1, %2, %3, {%5, %5, %5, %5}, p;\n\t}\n"
        :: "r"(d), "l"(a), "l"(b), "r"(idesc), "r"(en), "r"(0u) : "memory");
}
#define MBAR_WAIT_PARITY(addr, ph) do {                                          \
    uint32_t _m = (addr), _p = (ph), _done;                                      \
    asm volatile("{\n\t.reg .pred p;\n\t"                                        \
        "mbarrier.try_wait.parity.acquire.cta.shared::cta.b64 p, [%1], %2;\n\t"  \
        "selp.b32 %0, 1, 0, p;\n\t}" : "=r"(_done) : "r"(_m), "r"(_p) : "memory");\
    if (!_done) {                                                                \
        asm volatile("{\n\t.reg .pred P1;\n\t"                                   \
            "WL_%=:\n\t"                                                         \
            "mbarrier.try_wait.parity.acquire.cta.shared::cta.b64 P1, [%0], %1, 0x989680;\n\t" \
            "@P1 bra.uni WD_%=;\n\tbra.uni WL_%=;\n\tWD_%=:\n\t}"                \
            :: "r"(_m), "r"(_p) : "memory");                                     \
    } } while (0)
#define LDTM_X32(r, addr)                                                        \
    asm volatile("tcgen05.ld.sync.aligned.32x32b.x32.b32 "                       \
        "{%0, %1, %2, %3, %4, %5, %6, %7, %8, %9, %10, %11, %12, %13, %14, %15," \
        " %16, %17, %18, %19, %20, %21, %22, %23, %24, %25, %26, %27, %28, %29, %30, %31}, [%32];" \
        : "=r"((r)[0]),  "=r"((r)[1]),  "=r"((r)[2]),  "=r"((r)[3]),             \
          "=r"((r)[4]),  "=r"((r)[5]),  "=r"((r)[6]),  "=r"((r)[7]),             \
          "=r"((r)[8]),  "=r"((r)[9]),  "=r"((r)[10]), "=r"((r)[11]),            \
          "=r"((r)[12]), "=r"((r)[13]), "=r"((r)[14]), "=r"((r)[15]),            \
          "=r"((r)[16]), "=r"((r)[17]), "=r"((r)[18]), "=r"((r)[19]),            \
          "=r"((r)[20]), "=r"((r)[21]), "=r"((r)[22]), "=r"((r)[23]),            \
          "=r"((r)[24]), "=r"((r)[25]), "=r"((r)[26]), "=r"((r)[27]),            \
          "=r"((r)[28]), "=r"((r)[29]), "=r"((r)[30]), "=r"((r)[31])             \
        : "r"(addr))
#define IDESC_TF32 0x08100910u
#define DESC_BASE ((2ull << 61) | (1ull << 46) | (64ull << 32) | (1ull << 16))
__device__ __forceinline__ uint64_t mk_desc(uint32_t addr) {
    return DESC_BASE | ((uint64_t)(addr >> 4) & 0x3FFF);
}
#endif

// decoder dynamic smem layout (from 1024-aligned base); per-CTA (1 edge-type)
#define OFF_B     0          // 16384 (W2T, SW128)
#define OFF_A     16384      // 32768 (h1 tile, SW128)
#define DEC_DYN   (16384 + 32768 + 1024)

// node-MLP kernel smem (float indices)
#define NOFF_W1   0
#define NOFF_W2   5120
#define NOFF_W3   9216
#define NOFF_B    10240
#define NOFF_AUG  10384      // 64*81
#define NOFF_H1   15568      // 64*65
#define NOFF_H2   19728      // 64*65
#define NODE_DYN  (23888 * 4)

// ---------------------------------------------------------------------------
// uv + fused w2t: grid (16, BB), 256 threads, 8 nodes per CTA (low regs).
// ---------------------------------------------------------------------------
__global__ __launch_bounds__(256) void uv_kernel(
    const float* __restrict__ inp, const float* __restrict__ W1,
    const float* __restrict__ b1, const float* __restrict__ W2)
{
    const int g = blockIdx.x, b = blockIdx.y;
    const int n0 = g * 8;
    const int t = threadIdx.x;
    const int k = t >> 6, h = t & 63;

    if (b == 0) {   // fused w2t: 16 groups x 1024 elements = 16384 total
        for (int idx = g * 1024 + t; idx < (g + 1) * 1024; idx += 256) {
            const int kk2 = idx >> 12, rem = idx & 4095, kki = rem >> 6, m = rem & 63;
            ((uint32_t*)g_W2T)[(kk2 * MOUT + m) * MHID + kki] =
                f2tf32(W2[(kk2 * MHID + kki) * MOUT + m]);
        }
    }

    __shared__ float xs[8][NIN];
    if (t < 128) {
        const int nn = t & 7, f = t >> 3;
        xs[nn][f] = inp[(b * NIN + f) * NN + n0 + nn];
    }
    __syncthreads();

    const float* w = W1 + k * (2 * NIN) * MHID;
    const float bv = b1[k * MHID + h];
    float u[8], v[8];
#pragma unroll
    for (int nn = 0; nn < 8; nn++) { u[nn] = 0.f; v[nn] = bv; }
#pragma unroll
    for (int f = 0; f < NIN; f++) {
        const float wu = w[f * MHID + h];
        const float wv = w[(NIN + f) * MHID + h];
#pragma unroll
        for (int nn = 0; nn < 8; nn++) {
            u[nn] = fmaf(xs[nn][f], wu, u[nn]);
            v[nn] = fmaf(xs[nn][f], wv, v[nn]);
        }
    }
#pragma unroll
    for (int nn = 0; nn < 8; nn++) {
        g_U[((b * NN + n0 + nn) * KT + k) * MHID + h] = u[nn];
        g_V[((b * NN + n0 + nn) * KT + k) * MHID + h] = v[nn];
    }
}

// ---------------------------------------------------------------------------
// Persistent k-split decoder: grid 592, 256 threads, 4 CTAs per SM.
// CTA kp = blockIdx.x & 3 owns edge-type kp. ALL 8 warps build A(tc), then
// ALL 8 warps run epilogue(tc-1) from the other TMEM bank while GEMM(tc)
// executes. TMEM 128 cols/CTA (2 banks of 64), 4 x 128 = 512 exact.
// ---------------------------------------------------------------------------
__global__ __launch_bounds__(256, 4) void decoder_kernel(
    const float* __restrict__ rel_types, const float* __restrict__ W2,
    const float* __restrict__ b2)
{
    extern __shared__ char dsm[];
    __shared__ __align__(8) float b2s[MOUT];
    __shared__ float part[4][MOUT];
    __shared__ uint32_t tmem_ptr_s;
    __shared__ __align__(8) uint64_t mbar[3];  // [0]=mma done, [1..2]=bank free

    const int t = threadIdx.x;
    const int wid = t >> 5, lane = t & 31;
    const int kp = blockIdx.x & 3;             // edge-type owned by this CTA
    const int tile0 = blockIdx.x >> 2;         // 0..147

    const uint32_t dyn = smem_u32(dsm);
    const uint32_t base = (dyn + 1023) & ~1023u;
    char* P = dsm + (base - dyn);

    if (t < 64) b2s[t] = b2[kp * 64 + t];

#if defined(__CUDA_ARCH_FEAT_SM103_ALL)
    const uint32_t mb_mma   = smem_u32(&mbar[0]);
    const uint32_t mb_free0 = smem_u32(&mbar[1]);
    const uint32_t mb_free1 = smem_u32(&mbar[2]);

    // stage this CTA's B tile (W2T, SW128) once
    for (int idx = t; idx < 64 * 16; idx += 256) {
        const int n = idx >> 4, c = (idx & 15) * 4;
        uint4 w4 = *(const uint4*)((const uint32_t*)g_W2T + (kp * MOUT + n) * MHID + c);
        uint32_t byte = ((n >> 3) + (c >> 5) * 8) * 1024 + (n & 7) * 128 + (c & 31) * 4;
        byte ^= (byte >> 3) & 0x70;
        *(uint4*)(P + OFF_B + byte) = w4;
    }
    if (t == 0) {
        asm volatile("mbarrier.init.shared.b64 [%0], 1;" :: "r"(mb_mma) : "memory");
        asm volatile("mbarrier.init.shared.b64 [%0], 1;" :: "r"(mb_free0) : "memory");
        asm volatile("mbarrier.init.shared.b64 [%0], 1;" :: "r"(mb_free1) : "memory");
    }
    if (wid == 0) {
        asm volatile("tcgen05.alloc.cta_group::1.sync.aligned.shared::cta.b32 [%0], %1;"
                     :: "r"(smem_u32(&tmem_ptr_s)), "r"(128u) : "memory");
        asm volatile("tcgen05.relinquish_alloc_permit.cta_group::1.sync.aligned;");
    }
    __syncthreads();
    const uint32_t tmem = tmem_ptr_s;

    // build constants: col group cg (4 floats), row group rg (0..15);
    // rows rg + 16*it keep r&7 constant -> swizzled STS steps by +2048 B.
    const int cg = t & 15;
    const int rg = t >> 4;
    const uint32_t stsoff = ((cg >= 8) ? 16384u : 0u) + (uint32_t)(rg >> 3) * 1024u
                          + (uint32_t)(rg & 7) * 128u
                          + ((uint32_t)((cg & 7) ^ (rg & 7)) << 4);
    const float* ubase = g_U + rg * (KT * MHID) + kp * MHID + cg * 4;
    const float* vbase = g_V + kp * MHID + cg * 4;

    // epilogue constants: warp (sub, chv)
    const int sub = wid & 3;                // TMEM subpartition
    const int chv = wid >> 2;               // 32-col chunk
    const int jrow = sub * 32 + lane;       // node j

    int phM = 0, phF0 = 0, phF1 = 0, tc = 0;
    int pb = 0, pi = 0;

    // epilogue for tile (eb, ei) whose D sits in TMEM bank eq
    auto do_epilogue = [&](int eb, int ei, int eq) {
        float rt = 0.f;
        if (jrow != ei) {
            const int e = ei * (NN - 1) + jrow - (jrow > ei);
            rt = rel_types[((size_t)eb * EDGES + e) * KT + kp];
        }
        unsigned long long rtp;
        asm("mov.b64 %0, {%1, %1};" : "=l"(rtp) : "r"(__float_as_uint(rt)));
        asm volatile("tcgen05.fence::after_thread_sync;" ::: "memory");
        union { float f[32]; unsigned long long u[16]; uint32_t w[32]; } A;
        LDTM_X32(A.w, tmem + eq * 64 + chv * 32);
        asm volatile("tcgen05.wait::ld.sync.aligned;" ::: "memory");
        const unsigned long long* b2p = (const unsigned long long*)&b2s[chv * 32];
#pragma unroll
        for (int p = 0; p < 16; p++)
            asm("add.rn.f32x2 %0, %0, %1;" : "+l"(A.u[p]) : "l"(b2p[p]));
#pragma unroll
        for (int c = 0; c < 32; c++) A.f[c] = fmaxf(A.f[c], 0.f);
#pragma unroll
        for (int p = 0; p < 16; p++)
            asm("mul.rn.f32x2 %0, %0, %1;" : "+l"(A.u[p]) : "l"(rtp));
        // packed split-butterfly, levels 16..2
#pragma unroll
        for (int o = 16; o >= 2; o >>= 1) {
            const bool up = (lane & o) != 0;
            const int hq = o >> 1;
#pragma unroll
            for (int q2 = 0; q2 < 16; q2++) {
                if (q2 >= hq) break;
                const unsigned long long send = up ? A.u[q2] : A.u[q2 + hq];
                unsigned long long keep = up ? A.u[q2 + hq] : A.u[q2];
                const unsigned long long rs = __shfl_xor_sync(0xFFFFFFFFu, send, o);
                asm("add.rn.f32x2 %0, %0, %1;" : "+l"(keep) : "l"(rs));
                A.u[q2] = keep;
            }
        }
        {   // final level (o=1)
            const bool up = (lane & 1) != 0;
            const float send = up ? A.f[0] : A.f[1];
            const float keep = up ? A.f[1] : A.f[0];
            part[sub][chv * 32 + lane] = keep + __shfl_xor_sync(0xFFFFFFFFu, send, 1);
        }
        asm volatile("tcgen05.fence::before_thread_sync;" ::: "memory");
        __syncthreads();
        if (t == 0) {   // bank eq recyclable
            if (eq == 0)
                asm volatile("mbarrier.arrive.shared.b64 _, [%0];" :: "r"(mb_free0) : "memory");
            else
                asm volatile("mbarrier.arrive.shared.b64 _, [%0];" :: "r"(mb_free1) : "memory");
        }
        if (t < 64)
            g_AGGp[kp][(eb * NN + ei) * MOUT + t] =
                part[0][t] + part[1][t] + part[2][t] + part[3][t];
    };

    for (int tile = tile0; tile < BB * NN; tile += 148, tc++) {
        const int b = tile >> 7, i = tile & 127;
        const int q = tc & 1;

        const float4 vv = *(const float4*)(vbase + (b * NN + i) * (KT * MHID));

        // GEMM(tc-1) done: A free + bank q^1 ready for epilogue
        if (tc > 0) { MBAR_WAIT_PARITY(mb_mma, phM); phM ^= 1; }

        // ---- build A(tc), all 8 warps, 8 uint4 each ----
        {
            const float* us = ubase + b * (NN * KT * MHID);
            char* sp = P + OFF_A + stsoff;
#pragma unroll
            for (int it = 0; it < 8; it++, sp += 2048, us += 16 * KT * MHID) {
                const float4 u = *(const float4*)us;
                uint4 w4;   // raw fp32 — tcgen05 tf32 truncates in-HW
                w4.x = __float_as_uint(fmaxf(u.x + vv.x, 0.f));
                w4.y = __float_as_uint(fmaxf(u.y + vv.y, 0.f));
                w4.z = __float_as_uint(fmaxf(u.z + vv.z, 0.f));
                w4.w = __float_as_uint(fmaxf(u.w + vv.w, 0.f));
                *(uint4*)sp = w4;
            }
        }
        __syncthreads();

        // ---- issue GEMM(tc) into bank q ----
        if (t == 0) {
            if (tc >= 2) {   // epilogue(tc-2) must have released bank q
                if (q == 0) { MBAR_WAIT_PARITY(mb_free0, phF0); phF0 ^= 1; }
                else        { MBAR_WAIT_PARITY(mb_free1, phF1); phF1 ^= 1; }
            }
            asm volatile("fence.proxy.async.shared::cta;" ::: "memory");
            const uint64_t ad = mk_desc(base + OFF_A);
            const uint64_t bd = mk_desc(base + OFF_B);
            const uint32_t dcol = tmem + q * 64;
#pragma unroll
            for (int s = 0; s < 8; s++)
                mma_tf32_ss(dcol,
                            ad + ((s >> 2) ? 1024u : 0u) + (s & 3) * 2,
                            bd + ((s >> 2) ? 512u : 0u) + (s & 3) * 2,
                            IDESC_TF32, (uint32_t)(s > 0));
            asm volatile(
                "tcgen05.commit.cta_group::1.mbarrier::arrive::one.shared::cluster.b64 [%0];"
                :: "r"(mb_mma) : "memory");
        }

        // ---- epilogue(tc-1) from bank q^1 (overlaps GEMM(tc)) ----
        if (tc > 0) do_epilogue(pb, pi, q ^ 1);

        pb = b; pi = i;
    }
    if (tc > 0) {   // drain last tile
        MBAR_WAIT_PARITY(mb_mma, phM); phM ^= 1;
        do_epilogue(pb, pi, (tc - 1) & 1);
    }

    __syncthreads();
    if (t == 0) {
        asm volatile("mbarrier.inval.shared.b64 [%0];" :: "r"(mb_mma) : "memory");
        asm volatile("mbarrier.inval.shared.b64 [%0];" :: "r"(mb_free0) : "memory");
        asm volatile("mbarrier.inval.shared.b64 [%0];" :: "r"(mb_free1) : "memory");
    }
    if (wid == 0)
        asm volatile("tcgen05.dealloc.cta_group::1.sync.aligned.b32 %0, %1;"
                     :: "r"(tmem), "r"(128u));
#else
    // ============ SIMT fallback (compile-only for plain sm_103) ============
    __shared__ float vs0[MHID];
    __shared__ float rts0[NN];
    float* h1  = (float*)P;                  // [128][68]
    float* W2s = (float*)(P + 128 * 68 * 4); // fallback-only layout

    for (int tile = tile0; tile < BB * NN; tile += 148) {
        const int b = tile >> 7, i = tile & 127;
        __syncthreads();
        if (t < 64) vs0[t] = g_V[((b * NN + i) * KT + kp) * MHID + t];
        for (int j = t; j < NN; j += 256) {
            float rt = 0.f;
            if (j != i) {
                const int e = i * (NN - 1) + j - (j > i);
                rt = rel_types[((size_t)b * EDGES + e) * KT + kp];
            }
            rts0[j] = rt;
        }
        __syncthreads();
        for (int idx = t; idx < 128 * 64; idx += 256) {
            const int rr = idx >> 6, h = idx & 63;
            h1[rr * 68 + h] = fmaxf(
                g_U[((b * NN + rr) * KT + kp) * MHID + h] + vs0[h], 0.f);
        }
        for (int idx = t; idx < 64 * 64; idx += 256)
            W2s[idx] = W2[kp * 64 * 64 + idx];
        __syncthreads();
        const int r = t >> 1, cq = (t & 1) * 32;
        float acc[32];
#pragma unroll
        for (int c = 0; c < 32; c++) acc[c] = 0.f;
        for (int kkk = 0; kkk < 64; kkk++) {
            const float a = h1[r * 68 + kkk];
#pragma unroll
            for (int c = 0; c < 32; c++)
                acc[c] = fmaf(a, W2s[kkk * 64 + cq + c], acc[c]);
        }
        const float rt = rts0[r];
        __syncthreads();
        float* red = (float*)P;  // [64 m][stride 132]
#pragma unroll
        for (int c = 0; c < 32; c++)
            red[(cq + c) * 132 + r] = rt * fmaxf(acc[c] + b2s[cq + c], 0.f);
        __syncthreads();
        if (t < 64) {
            float s = 0.f;
            for (int l = 0; l < 128; l++) s += red[t * 132 + l];
            g_AGGp[kp][(b * NN + i) * MOUT + t] = s;
        }
        __syncthreads();
    }
#endif
}

// ---------------------------------------------------------------------------
// Node MLP: grid 64 (64 nodes/CTA), 256 threads, weights staged once.
// ---------------------------------------------------------------------------
__global__ __launch_bounds__(256) void node_kernel(
    const float* __restrict__ inp,
    const float* __restrict__ Wo1, const float* __restrict__ bo1,
    const float* __restrict__ Wo2, const float* __restrict__ bo2,
    const float* __restrict__ Wo3, const float* __restrict__ bo3,
    float* __restrict__ out)
{
    extern __shared__ float nsm[];
    float* sW1 = nsm + NOFF_W1;
    float* sW2 = nsm + NOFF_W2;
    float* sW3 = nsm + NOFF_W3;
    float* sB  = nsm + NOFF_B;
    float* aug = nsm + NOFF_AUG;   // [64][81]
    float* h1  = nsm + NOFF_H1;    // [64][65]
    float* h2  = nsm + NOFF_H2;    // [64][65]

    const int t = threadIdx.x;
    const int b = blockIdx.x >> 1, n0 = (blockIdx.x & 1) * 64;

    for (int idx = t; idx < 80 * 64; idx += 256) sW1[idx] = Wo1[idx];
    for (int idx = t; idx < 64 * 64; idx += 256) sW2[idx] = Wo2[idx];
    for (int idx = t; idx < 64 * 16; idx += 256) sW3[idx] = Wo3[idx];
    if (t < 64) sB[t] = bo1[t];
    if (t < 64) sB[64 + t] = bo2[t];
    if (t < 16) sB[128 + t] = bo3[t];

    {
        const int nn = t >> 2, f0 = (t & 3) * 20;
#pragma unroll
        for (int f = f0; f < f0 + 20; f++) {
            float val;
            if (f < NIN) {
                val = inp[(b * NIN + f) * NN + (n0 + nn)];
            } else {
                const int idx = (b * NN + n0 + nn) * MOUT + (f - NIN);
                val = (g_AGGp[0][idx] + g_AGGp[1][idx]) +
                      (g_AGGp[2][idx] + g_AGGp[3][idx]);
            }
            aug[nn * 81 + f] = val;
        }
    }
    __syncthreads();

    const int nn = t & 63, s = t >> 6;
    {
        float acc[16];
#pragma unroll
        for (int x = 0; x < 16; x++) acc[x] = sB[s * 16 + x];
        for (int f = 0; f < NIN + MOUT; f++) {
            const float a = aug[nn * 81 + f];
#pragma unroll
            for (int x = 0; x < 16; x++)
                acc[x] = fmaf(a, sW1[f * 64 + s * 16 + x], acc[x]);
        }
#pragma unroll
        for (int x = 0; x < 16; x++) h1[nn * 65 + s * 16 + x] = fmaxf(acc[x], 0.f);
    }
    __syncthreads();
    {
        float acc[16];
#pragma unroll
        for (int x = 0; x < 16; x++) acc[x] = sB[64 + s * 16 + x];
        for (int f = 0; f < NHID; f++) {
            const float a = h1[nn * 65 + f];
#pragma unroll
            for (int x = 0; x < 16; x++)
                acc[x] = fmaf(a, sW2[f * 64 + s * 16 + x], acc[x]);
        }
#pragma unroll
        for (int x = 0; x < 16; x++) h2[nn * 65 + s * 16 + x] = fmaxf(acc[x], 0.f);
    }
    __syncthreads();
    {
        float acc[4];
#pragma unroll
        for (int x = 0; x < 4; x++) acc[x] = sB[128 + s * 4 + x];
        for (int f = 0; f < NHID; f++) {
            const float a = h2[nn * 65 + f];
#pragma unroll
            for (int x = 0; x < 4; x++)
                acc[x] = fmaf(a, sW3[f * 16 + s * 4 + x], acc[x]);
        }
#pragma unroll
        for (int x = 0; x < 4; x++)
            out[(b * NOUT + s * 4 + x) * NN + (n0 + nn)] = acc[x];
    }
}

// ---------------------------------------------------------------------------
extern "C" void kernel_launch(void* const* d_in, const int* in_sizes, int n_in,
                              void* d_out, int out_size)
{
    const float* inp       = (const float*)d_in[0];
    const float* rel_types = (const float*)d_in[3];
    const float* W1  = (const float*)d_in[4];
    const float* b1  = (const float*)d_in[5];
    const float* W2  = (const float*)d_in[6];
    const float* b2  = (const float*)d_in[7];
    const float* Wo1 = (const float*)d_in[8];
    const float* bo1 = (const float*)d_in[9];
    const float* Wo2 = (const float*)d_in[10];
    const float* bo2 = (const float*)d_in[11];
    const float* Wo3 = (const float*)d_in[12];
    const float* bo3 = (const float*)d_in[13];
    float* out = (float*)d_out;

    (void)cudaFuncSetAttribute(decoder_kernel,
                               cudaFuncAttributeMaxDynamicSharedMemorySize, DEC_DYN);
    (void)cudaFuncSetAttribute(node_kernel,
                               cudaFuncAttributeMaxDynamicSharedMemorySize, NODE_DYN);

    uv_kernel<<<dim3(16, BB), 256>>>(inp, W1, b1, W2);
    decoder_kernel<<<592, 256, DEC_DYN>>>(rel_types, W2, b2);
    node_kernel<<<64, 256, NODE_DYN>>>(inp, Wo1, bo1, Wo2, bo2, Wo3, bo3, out);
}